// round 1
// baseline (speedup 1.0000x reference)
#include <cuda_runtime.h>
#include <cuda_bf16.h>

#define T_STEPS 256
#define BATCH   128
#define DIM_IN  512
#define HID     512
#define NQ      8
#define QDIM    256   // 2^8

// ---------------- scratch (no allocations allowed) ----------------
__device__ float4 g_xdot[T_STEPS * BATCH];   // per (t,b): dots for f,i,g,o
__device__ float  g_H[T_STEPS * BATCH];      // scalar hidden state per (t,b)
__device__ float  g_Cfin[BATCH];             // final cell scalar per b
__device__ float  g_par[4][5];               // per gate: alpha, beta, gamma, wsum, b0

__device__ __forceinline__ float2 cmul(float2 a, float2 b) {
    return make_float2(a.x * b.x - a.y * b.y, a.x * b.y + a.y * b.x);
}
__device__ __forceinline__ float2 cadd(float2 a, float2 b) {
    return make_float2(a.x + b.x, a.y + b.y);
}

// ---------------- Kernel A: simulate the 4 variational circuits ----------------
// One block per gate (f,i,g,o). Computes columns 0 and 128 of the unitary via
// statevector simulation, then reduces to the 3 scalars of
//   expval(theta) = alpha + beta*cos(theta) + gamma*sin(theta),
// plus wsum = sum(W[0,512:1024]) and b0 = b[0].
__global__ void circuit_kernel(
    const float* __restrict__ Pf, const float* __restrict__ Pi,
    const float* __restrict__ Pg, const float* __restrict__ Po,
    const float* __restrict__ Wf, const float* __restrict__ Wi,
    const float* __restrict__ Wg, const float* __restrict__ Wo,
    const float* __restrict__ bfv, const float* __restrict__ biv,
    const float* __restrict__ bgv, const float* __restrict__ bov)
{
    int g = blockIdx.x;
    const float* P  = (g == 0) ? Pf : (g == 1) ? Pi : (g == 2) ? Pg : Po;
    const float* W  = (g == 0) ? Wf : (g == 1) ? Wi : (g == 2) ? Wg : Wo;
    const float* bv = (g == 0) ? bfv : (g == 1) ? biv : (g == 2) ? bgv : bov;

    __shared__ float2 a0[QDIM], a1[QDIM];
    __shared__ float  r0[QDIM], r1[QDIM], r2[QDIM];
    int d = threadIdx.x;

    // init: column 0 -> |0>, column 128 -> |128>
    a0[d] = make_float2(d == 0 ? 1.f : 0.f, 0.f);
    a1[d] = make_float2(d == QDIM / 2 ? 1.f : 0.f, 0.f);

    for (int l = 0; l < 2; l++) {
        // 8 single-qubit rotations (qubit w occupies bit 7-w, MSB-first kron order)
        for (int w = 0; w < NQ; w++) {
            const float* p = P + (l * NQ + w) * 3;
            float phi = p[0], th = p[1], om = p[2];
            float c = cosf(0.5f * th), s = sinf(0.5f * th);
            float ap = 0.5f * (phi + om), bm = 0.5f * (phi - om);
            float cap = cosf(ap), sap = sinf(ap);
            float cbm = cosf(bm), sbm = sinf(bm);
            // ep = e^{-i(phi+om)/2}; em = e^{+i(phi-om)/2}
            float2 m00 = make_float2(cap * c, -sap * c);     // ep*c
            float2 m01 = make_float2(-cbm * s, -sbm * s);    // -em*s
            float2 m10 = make_float2(cbm * s, -sbm * s);     // conj(em)*s
            float2 m11 = make_float2(cap * c, sap * c);      // conj(ep)*c

            int p7 = 7 - w;
            int mask = 1 << p7;
            int bit = (d >> p7) & 1;
            __syncthreads();
            float2 me0 = a0[d], pa0 = a0[d ^ mask];
            float2 me1 = a1[d], pa1 = a1[d ^ mask];
            __syncthreads();
            float2 n0, n1;
            if (!bit) {
                n0 = cadd(cmul(m00, me0), cmul(m01, pa0));
                n1 = cadd(cmul(m00, me1), cmul(m01, pa1));
            } else {
                n0 = cadd(cmul(m10, pa0), cmul(m11, me0));
                n1 = cadd(cmul(m10, pa1), cmul(m11, me1));
            }
            a0[d] = n0; a1[d] = n1;
        }
        // CNOT chain: control qubit w (bit 7-w), target w+1 (bit 6-w), w=0..6 in order
        for (int w = 0; w < NQ - 1; w++) {
            int pc = 7 - w, pt = 6 - w;
            __syncthreads();
            int src = ((d >> pc) & 1) ? (d ^ (1 << pt)) : d;
            float2 v0 = a0[src], v1 = a1[src];
            __syncthreads();
            a0[d] = v0; a1[d] = v1;
        }
    }
    __syncthreads();

    float z = (d < QDIM / 2) ? 1.f : -1.f;
    float2 c0 = a0[d], c1 = a1[d];
    r0[d] = z * (c0.x * c0.x + c0.y * c0.y);          // Z-weighted |c0|^2
    r1[d] = z * (c1.x * c1.x + c1.y * c1.y);          // Z-weighted |c1|^2
    r2[d] = z * (c0.y * c1.x - c0.x * c1.y);          // Z-weighted Im(c0 * conj(c1))
    __syncthreads();
    for (int off = QDIM / 2; off; off >>= 1) {
        if (d < off) { r0[d] += r0[d + off]; r1[d] += r1[d + off]; r2[d] += r2[d + off]; }
        __syncthreads();
    }
    float S00 = r0[0], S11 = r1[0], S01 = r2[0];
    __syncthreads();

    // wsum = sum over W[0][512..1023]
    r0[d] = W[512 + d] + W[512 + QDIM + d];
    __syncthreads();
    for (int off = QDIM / 2; off; off >>= 1) {
        if (d < off) r0[d] += r0[d + off];
        __syncthreads();
    }
    if (d == 0) {
        g_par[g][0] = 0.5f * (S00 + S11);   // alpha
        g_par[g][1] = 0.5f * (S00 - S11);   // beta
        g_par[g][2] = -S01;                 // gamma
        g_par[g][3] = r0[0];                // wsum
        g_par[g][4] = bv[0];                // b0
    }
}

// ---------------- Kernel B: xdot[t,b][g] = inputs[t,b,:] . W_g[0,0:512] ----------------
// One warp per (t,b) row. 67 MB streamed read; HBM-bound.
__global__ void xdot_kernel(
    const float* __restrict__ X,
    const float* __restrict__ Wf, const float* __restrict__ Wi,
    const float* __restrict__ Wg, const float* __restrict__ Wo)
{
    int warp = (blockIdx.x * blockDim.x + threadIdx.x) >> 5;
    int lane = threadIdx.x & 31;
    if (warp >= T_STEPS * BATCH) return;

    const float4* xr = (const float4*)(X + (size_t)warp * DIM_IN);
    const float4* wf = (const float4*)Wf;
    const float4* wi = (const float4*)Wi;
    const float4* wg = (const float4*)Wg;
    const float4* wo = (const float4*)Wo;

    float sf = 0.f, si = 0.f, sg = 0.f, so = 0.f;
#pragma unroll
    for (int j = 0; j < 4; j++) {
        int k = lane + 32 * j;
        float4 xv = xr[k];
        float4 a = __ldg(wf + k); sf += xv.x * a.x + xv.y * a.y + xv.z * a.z + xv.w * a.w;
        float4 b = __ldg(wi + k); si += xv.x * b.x + xv.y * b.y + xv.z * b.z + xv.w * b.w;
        float4 c = __ldg(wg + k); sg += xv.x * c.x + xv.y * c.y + xv.z * c.z + xv.w * c.w;
        float4 e = __ldg(wo + k); so += xv.x * e.x + xv.y * e.y + xv.z * e.z + xv.w * e.w;
    }
#pragma unroll
    for (int o = 16; o; o >>= 1) {
        sf += __shfl_xor_sync(0xffffffffu, sf, o);
        si += __shfl_xor_sync(0xffffffffu, si, o);
        sg += __shfl_xor_sync(0xffffffffu, sg, o);
        so += __shfl_xor_sync(0xffffffffu, so, o);
    }
    if (lane == 0) g_xdot[warp] = make_float4(sf, si, sg, so);
}

// ---------------- Kernel C: scalar LSTM scan ----------------
// 128 independent scalar recurrences (one per batch element), 256 steps.
// 4-deep register prefetch hides L2 latency of the xdot reads.
__device__ __forceinline__ float fsig(float v) {
    return __fdividef(1.f, 1.f + __expf(-v));
}
__device__ __forceinline__ float ftanh(float v) {
    return 1.f - __fdividef(2.f, __expf(2.f * v) + 1.f);
}

__global__ void scan_kernel()
{
    int b = threadIdx.x;

    float al_f = g_par[0][0], be_f = g_par[0][1], ga_f = g_par[0][2], ws_f = g_par[0][3], b0_f = g_par[0][4];
    float al_i = g_par[1][0], be_i = g_par[1][1], ga_i = g_par[1][2], ws_i = g_par[1][3], b0_i = g_par[1][4];
    float al_g = g_par[2][0], be_g = g_par[2][1], ga_g = g_par[2][2], ws_g = g_par[2][3], b0_g = g_par[2][4];
    float al_o = g_par[3][0], be_o = g_par[3][1], ga_o = g_par[3][2], ws_o = g_par[3][3], b0_o = g_par[3][4];

    float H = 0.f, C = 0.f;

    const float4* X = g_xdot;
    float4 q0 = X[0 * BATCH + b];
    float4 q1 = X[1 * BATCH + b];
    float4 q2 = X[2 * BATCH + b];
    float4 q3 = X[3 * BATCH + b];

#define STEP(xd, t)                                                              \
    {                                                                            \
        float sf_, cf_; __sincosf((xd).x + H * ws_f + b0_f, &sf_, &cf_);         \
        float si_, ci_; __sincosf((xd).y + H * ws_i + b0_i, &si_, &ci_);         \
        float sg_, cg_; __sincosf((xd).z + H * ws_g + b0_g, &sg_, &cg_);         \
        float so_, co_; __sincosf((xd).w + H * ws_o + b0_o, &so_, &co_);         \
        float fv = fsig(al_f + be_f * cf_ + ga_f * sf_);                         \
        float iv = fsig(al_i + be_i * ci_ + ga_i * si_);                         \
        float gv = ftanh(al_g + be_g * cg_ + ga_g * sg_);                        \
        float ov = fsig(al_o + be_o * co_ + ga_o * so_);                         \
        C = fv * C + iv * gv;                                                    \
        H = ov * ftanh(C);                                                       \
        g_H[(t) * BATCH + b] = H;                                                \
    }

#pragma unroll 1
    for (int t = 0; t < T_STEPS; t += 4) {
        float4 c0 = q0; if (t + 4 < T_STEPS) q0 = X[(t + 4) * BATCH + b];
        STEP(c0, t);
        float4 c1 = q1; if (t + 5 < T_STEPS) q1 = X[(t + 5) * BATCH + b];
        STEP(c1, t + 1);
        float4 c2 = q2; if (t + 6 < T_STEPS) q2 = X[(t + 6) * BATCH + b];
        STEP(c2, t + 2);
        float4 c3 = q3; if (t + 7 < T_STEPS) q3 = X[(t + 7) * BATCH + b];
        STEP(c3, t + 3);
    }
#undef STEP
    g_Cfin[b] = C;
}

// ---------------- Kernel D: broadcast scalars into the full output ----------------
// d_out layout: outputs (T,B,512) ++ hx (B,512) ++ cx (B,512). 67 MB write.
__global__ void bcast_kernel(float4* __restrict__ out)
{
    unsigned i = blockIdx.x * blockDim.x + threadIdx.x;   // float4 index
    const unsigned OUT4 = (unsigned)T_STEPS * BATCH * (HID / 4); // 4,194,304
    const unsigned HB4  = (unsigned)BATCH * (HID / 4);           // 16,384
    float v;
    if (i < OUT4) {
        v = g_H[i >> 7];                                    // (t*B+b) = i / 128
    } else if (i < OUT4 + HB4) {
        v = g_H[(T_STEPS - 1) * BATCH + ((i - OUT4) >> 7)]; // hx = last h
    } else if (i < OUT4 + 2 * HB4) {
        v = g_Cfin[(i - OUT4 - HB4) >> 7];                  // cx
    } else {
        return;
    }
    out[i] = make_float4(v, v, v, v);
}

// ---------------- launch ----------------
extern "C" void kernel_launch(void* const* d_in, const int* in_sizes, int n_in,
                              void* d_out, int out_size)
{
    const float* X  = (const float*)d_in[0];
    const float* Wf = (const float*)d_in[1];
    const float* bf = (const float*)d_in[2];
    const float* Pf = (const float*)d_in[3];
    const float* Wi = (const float*)d_in[4];
    const float* bi = (const float*)d_in[5];
    const float* Pi = (const float*)d_in[6];
    const float* Wg = (const float*)d_in[7];
    const float* bg = (const float*)d_in[8];
    const float* Pg = (const float*)d_in[9];
    const float* Wo = (const float*)d_in[10];
    const float* bo = (const float*)d_in[11];
    const float* Po = (const float*)d_in[12];

    circuit_kernel<<<4, QDIM>>>(Pf, Pi, Pg, Po, Wf, Wi, Wg, Wo, bf, bi, bg, bo);

    // 32768 rows, one warp each -> 4096 blocks of 256 threads
    xdot_kernel<<<(T_STEPS * BATCH) / 8, 256>>>(X, Wf, Wi, Wg, Wo);

    scan_kernel<<<1, BATCH>>>();

    // total float4s = 4,194,304 + 2*16,384 = 4,227,072 = 16512 * 256
    bcast_kernel<<<16512, 256>>>((float4*)d_out);
}

// round 3
// speedup vs baseline: 1.0906x; 1.0906x over previous
#include <cuda_runtime.h>
#include <cuda_bf16.h>

#define T_STEPS 256
#define BATCH   128
#define DIM_IN  512
#define HID     512
#define NQ      8
#define QDIM    256   // 2^8

// ---------------- scratch (no allocations allowed) ----------------
__device__ float4 g_xdot[T_STEPS * BATCH];   // per (t,b): theta offsets for f,i,g,o (bias+phi folded)
__device__ float  g_H[T_STEPS * BATCH];      // scalar hidden state per (t,b)
__device__ float  g_Cfin[BATCH];             // final cell scalar per b
// per gate: [0]=wsum  [1]=b0-phi  [2]=alpha/2  [3]=R/2  [4]=alpha  [5]=R
__device__ float  g_par[4][6];

__device__ __forceinline__ float2 cmul(float2 a, float2 b) {
    return make_float2(a.x * b.x - a.y * b.y, a.x * b.y + a.y * b.x);
}
__device__ __forceinline__ float2 cadd(float2 a, float2 b) {
    return make_float2(a.x + b.x, a.y + b.y);
}
__device__ __forceinline__ float htanh(float x) {
    float y;
    asm("tanh.approx.f32 %0, %1;" : "=f"(y) : "f"(x));
    return y;
}

// ---------------- Kernel A: simulate the 4 variational circuits ----------------
// One block per gate (f,i,g,o). Statevector-simulates columns 0 and 128 of the
// 2-layer circuit, then reduces to expval(theta) = alpha + R*cos(theta - phi),
// plus wsum = sum(W[0,512:1024]) and b0.
__global__ void circuit_kernel(
    const float* __restrict__ Pf, const float* __restrict__ Pi,
    const float* __restrict__ Pg, const float* __restrict__ Po,
    const float* __restrict__ Wf, const float* __restrict__ Wi,
    const float* __restrict__ Wg, const float* __restrict__ Wo,
    const float* __restrict__ bfv, const float* __restrict__ biv,
    const float* __restrict__ bgv, const float* __restrict__ bov)
{
    int g = blockIdx.x;
    const float* P  = (g == 0) ? Pf : (g == 1) ? Pi : (g == 2) ? Pg : Po;
    const float* W  = (g == 0) ? Wf : (g == 1) ? Wi : (g == 2) ? Wg : Wo;
    const float* bv = (g == 0) ? bfv : (g == 1) ? biv : (g == 2) ? bgv : bov;

    __shared__ float2 a0[QDIM], a1[QDIM];
    __shared__ float  r0[QDIM], r1[QDIM], r2[QDIM];
    int d = threadIdx.x;

    a0[d] = make_float2(d == 0 ? 1.f : 0.f, 0.f);
    a1[d] = make_float2(d == QDIM / 2 ? 1.f : 0.f, 0.f);

    for (int l = 0; l < 2; l++) {
        for (int w = 0; w < NQ; w++) {
            const float* p = P + (l * NQ + w) * 3;
            float phi = p[0], th = p[1], om = p[2];
            float c = cosf(0.5f * th), s = sinf(0.5f * th);
            float ap = 0.5f * (phi + om), bm = 0.5f * (phi - om);
            float cap = cosf(ap), sap = sinf(ap);
            float cbm = cosf(bm), sbm = sinf(bm);
            float2 m00 = make_float2(cap * c, -sap * c);     // ep*c
            float2 m01 = make_float2(-cbm * s, -sbm * s);    // -em*s
            float2 m10 = make_float2(cbm * s, -sbm * s);     // conj(em)*s
            float2 m11 = make_float2(cap * c, sap * c);      // conj(ep)*c

            int p7 = 7 - w;
            int mask = 1 << p7;
            int bit = (d >> p7) & 1;
            __syncthreads();
            float2 me0 = a0[d], pa0 = a0[d ^ mask];
            float2 me1 = a1[d], pa1 = a1[d ^ mask];
            __syncthreads();
            float2 n0, n1;
            if (!bit) {
                n0 = cadd(cmul(m00, me0), cmul(m01, pa0));
                n1 = cadd(cmul(m00, me1), cmul(m01, pa1));
            } else {
                n0 = cadd(cmul(m10, pa0), cmul(m11, me0));
                n1 = cadd(cmul(m10, pa1), cmul(m11, me1));
            }
            a0[d] = n0; a1[d] = n1;
        }
        for (int w = 0; w < NQ - 1; w++) {
            int pc = 7 - w, pt = 6 - w;
            __syncthreads();
            int src = ((d >> pc) & 1) ? (d ^ (1 << pt)) : d;
            float2 v0 = a0[src], v1 = a1[src];
            __syncthreads();
            a0[d] = v0; a1[d] = v1;
        }
    }
    __syncthreads();

    float z = (d < QDIM / 2) ? 1.f : -1.f;
    float2 c0 = a0[d], c1 = a1[d];
    r0[d] = z * (c0.x * c0.x + c0.y * c0.y);
    r1[d] = z * (c1.x * c1.x + c1.y * c1.y);
    r2[d] = z * (c0.y * c1.x - c0.x * c1.y);
    __syncthreads();
    for (int off = QDIM / 2; off; off >>= 1) {
        if (d < off) { r0[d] += r0[d + off]; r1[d] += r1[d + off]; r2[d] += r2[d + off]; }
        __syncthreads();
    }
    float S00 = r0[0], S11 = r1[0], S01 = r2[0];
    __syncthreads();

    r0[d] = W[512 + d] + W[512 + QDIM + d];
    __syncthreads();
    for (int off = QDIM / 2; off; off >>= 1) {
        if (d < off) r0[d] += r0[d + off];
        __syncthreads();
    }
    if (d == 0) {
        float alpha = 0.5f * (S00 + S11);
        float beta  = 0.5f * (S00 - S11);
        float gamma = -S01;
        float R   = sqrtf(beta * beta + gamma * gamma);
        float phi = atan2f(gamma, beta);
        g_par[g][0] = r0[0];          // wsum
        g_par[g][1] = bv[0] - phi;    // theta offset
        g_par[g][2] = 0.5f * alpha;
        g_par[g][3] = 0.5f * R;
        g_par[g][4] = alpha;
        g_par[g][5] = R;
    }
}

// ---------------- Kernel B: xdot[t,b][g] = X[t,b,:].W_g[0,0:512] + (b0-phi)_g ----------------
__global__ void xdot_kernel(
    const float* __restrict__ X,
    const float* __restrict__ Wf, const float* __restrict__ Wi,
    const float* __restrict__ Wg, const float* __restrict__ Wo)
{
    int warp = (blockIdx.x * blockDim.x + threadIdx.x) >> 5;
    int lane = threadIdx.x & 31;
    if (warp >= T_STEPS * BATCH) return;

    const float4* xr = (const float4*)(X + (size_t)warp * DIM_IN);
    const float4* wf = (const float4*)Wf;
    const float4* wi = (const float4*)Wi;
    const float4* wg = (const float4*)Wg;
    const float4* wo = (const float4*)Wo;

    float sf = 0.f, si = 0.f, sg = 0.f, so = 0.f;
#pragma unroll
    for (int j = 0; j < 4; j++) {
        int k = lane + 32 * j;
        float4 xv = xr[k];
        float4 a = __ldg(wf + k); sf += xv.x * a.x + xv.y * a.y + xv.z * a.z + xv.w * a.w;
        float4 b = __ldg(wi + k); si += xv.x * b.x + xv.y * b.y + xv.z * b.z + xv.w * b.w;
        float4 c = __ldg(wg + k); sg += xv.x * c.x + xv.y * c.y + xv.z * c.z + xv.w * c.w;
        float4 e = __ldg(wo + k); so += xv.x * e.x + xv.y * e.y + xv.z * e.z + xv.w * e.w;
    }
#pragma unroll
    for (int o = 16; o; o >>= 1) {
        sf += __shfl_xor_sync(0xffffffffu, sf, o);
        si += __shfl_xor_sync(0xffffffffu, si, o);
        sg += __shfl_xor_sync(0xffffffffu, sg, o);
        so += __shfl_xor_sync(0xffffffffu, so, o);
    }
    if (lane == 0) {
        g_xdot[warp] = make_float4(sf + g_par[0][1], si + g_par[1][1],
                                   sg + g_par[2][1], so + g_par[3][1]);
    }
}

// ---------------- Kernel C: scalar LSTM scan ----------------
// 128 independent scalar recurrences, 256 steps.
//   theta_g = xoff_g + H*ws_g ; gate = act(alpha_g + R_g*cos(theta_g))
// sigmoid(u) = 0.5 + 0.5*tanh(u/2) with alpha/2, R/2 pre-folded -> 1 cos + 1 tanh per gate.
__global__ void scan_kernel()
{
    int b = threadIdx.x;

    float ws_f = g_par[0][0], A2_f = g_par[0][2], R2_f = g_par[0][3];
    float ws_i = g_par[1][0], A2_i = g_par[1][2], R2_i = g_par[1][3];
    float ws_g = g_par[2][0], A_g  = g_par[2][4], R_g  = g_par[2][5];
    float ws_o = g_par[3][0], A2_o = g_par[3][2], R2_o = g_par[3][3];

    float H = 0.f, C = 0.f;

    const float4* X = g_xdot;
    float4 q0 = X[0 * BATCH + b];
    float4 q1 = X[1 * BATCH + b];
    float4 q2 = X[2 * BATCH + b];
    float4 q3 = X[3 * BATCH + b];

#define STEP(xd, t)                                                   \
    {                                                                 \
        float cf = __cosf(fmaf(H, ws_f, (xd).x));                     \
        float ci = __cosf(fmaf(H, ws_i, (xd).y));                     \
        float cg = __cosf(fmaf(H, ws_g, (xd).z));                     \
        float co = __cosf(fmaf(H, ws_o, (xd).w));                     \
        float fv = fmaf(htanh(fmaf(R2_f, cf, A2_f)), 0.5f, 0.5f);     \
        float iv = fmaf(htanh(fmaf(R2_i, ci, A2_i)), 0.5f, 0.5f);     \
        float gv = htanh(fmaf(R_g, cg, A_g));                         \
        float ov = fmaf(htanh(fmaf(R2_o, co, A2_o)), 0.5f, 0.5f);     \
        C = fmaf(fv, C, iv * gv);                                     \
        H = ov * htanh(C);                                            \
        g_H[(t) * BATCH + b] = H;                                     \
    }

#pragma unroll 1
    for (int t = 0; t < T_STEPS; t += 4) {
        float4 c0 = q0; if (t + 4 < T_STEPS) q0 = X[(t + 4) * BATCH + b];
        STEP(c0, t);
        float4 c1 = q1; if (t + 5 < T_STEPS) q1 = X[(t + 5) * BATCH + b];
        STEP(c1, t + 1);
        float4 c2 = q2; if (t + 6 < T_STEPS) q2 = X[(t + 6) * BATCH + b];
        STEP(c2, t + 2);
        float4 c3 = q3; if (t + 7 < T_STEPS) q3 = X[(t + 7) * BATCH + b];
        STEP(c3, t + 3);
    }
#undef STEP
    g_Cfin[b] = C;
}

// ---------------- Kernel D: broadcast scalars into the full output ----------------
// Each thread writes 4 consecutive float4s (64B) with streaming stores.
// d_out layout: outputs (T,B,512) ++ hx (B,512) ++ cx (B,512).
__global__ void bcast_kernel(float4* __restrict__ out)
{
    const unsigned OUT4 = (unsigned)T_STEPS * BATCH * (HID / 4); // 4,194,304
    const unsigned HB4  = (unsigned)BATCH * (HID / 4);           // 16,384
    unsigned base = (blockIdx.x * blockDim.x + threadIdx.x) * 4; // float4 index
    if (base >= OUT4 + 2 * HB4) return;

    float v;
    if (base < OUT4) {
        v = g_H[base >> 7];                                      // row = (t*B+b)
    } else if (base < OUT4 + HB4) {
        v = g_H[(T_STEPS - 1) * BATCH + ((base - OUT4) >> 7)];   // hx
    } else {
        v = g_Cfin[(base - OUT4 - HB4) >> 7];                    // cx
    }
    float4 v4 = make_float4(v, v, v, v);
    __stcs(out + base + 0, v4);
    __stcs(out + base + 1, v4);
    __stcs(out + base + 2, v4);
    __stcs(out + base + 3, v4);
}

// ---------------- launch ----------------
extern "C" void kernel_launch(void* const* d_in, const int* in_sizes, int n_in,
                              void* d_out, int out_size)
{
    const float* X  = (const float*)d_in[0];
    const float* Wf = (const float*)d_in[1];
    const float* bf = (const float*)d_in[2];
    const float* Pf = (const float*)d_in[3];
    const float* Wi = (const float*)d_in[4];
    const float* bi = (const float*)d_in[5];
    const float* Pi = (const float*)d_in[6];
    const float* Wg = (const float*)d_in[7];
    const float* bg = (const float*)d_in[8];
    const float* Pg = (const float*)d_in[9];
    const float* Wo = (const float*)d_in[10];
    const float* bo = (const float*)d_in[11];
    const float* Po = (const float*)d_in[12];

    circuit_kernel<<<4, QDIM>>>(Pf, Pi, Pg, Po, Wf, Wi, Wg, Wo, bf, bi, bg, bo);

    xdot_kernel<<<(T_STEPS * BATCH) / 8, 256>>>(X, Wf, Wi, Wg, Wo);

    scan_kernel<<<1, BATCH>>>();

    // (4,194,304 + 32,768) float4 / 4 per thread = 1,056,768 threads = 4128 * 256
    bcast_kernel<<<4128, 256>>>((float4*)d_out);
}

// round 4
// speedup vs baseline: 1.3335x; 1.2228x over previous
#include <cuda_runtime.h>
#include <cuda_bf16.h>

#define T_STEPS 256
#define BATCH   128
#define DIM_IN  512
#define HID     512
#define NQ      8
#define QDIM    256   // 2^8

// ---------------- scratch (no allocations allowed) ----------------
__device__ float4 g_xdot[T_STEPS * BATCH];   // per (t,b): raw dots for f,i,g,o
__device__ float  g_H[T_STEPS * BATCH];      // scalar hidden state per (t,b)
__device__ float  g_Cfin[BATCH];             // final cell scalar per b
// per gate: [0]=wsum  [1]=b0-phi  [2]=alpha/2  [3]=R/2  [4]=alpha  [5]=R
__device__ float  g_par[4][6];

__device__ __forceinline__ float2 cmul(float2 a, float2 b) {
    return make_float2(a.x * b.x - a.y * b.y, a.x * b.y + a.y * b.x);
}
__device__ __forceinline__ float2 cadd(float2 a, float2 b) {
    return make_float2(a.x + b.x, a.y + b.y);
}
__device__ __forceinline__ float htanh(float x) {
    float y;
    asm("tanh.approx.f32 %0, %1;" : "=f"(y) : "f"(x));
    return y;
}

// ---------------- circuit device func: simulate one variational circuit ----------------
// Statevector-simulates columns 0 and 128 of the 2-layer circuit, reduces to
// expval(theta) = alpha + R*cos(theta - phi), plus wsum and b0-phi.
__device__ void circuit_block(int g, const float* __restrict__ P,
                              const float* __restrict__ W, const float* __restrict__ bv)
{
    __shared__ float2 a0[QDIM], a1[QDIM];
    __shared__ float  r0[QDIM], r1[QDIM], r2[QDIM];
    int d = threadIdx.x;

    a0[d] = make_float2(d == 0 ? 1.f : 0.f, 0.f);
    a1[d] = make_float2(d == QDIM / 2 ? 1.f : 0.f, 0.f);

    for (int l = 0; l < 2; l++) {
        for (int w = 0; w < NQ; w++) {
            const float* p = P + (l * NQ + w) * 3;
            float phi = p[0], th = p[1], om = p[2];
            float c, s;  __sincosf(0.5f * th, &s, &c);
            float cap, sap; __sincosf(0.5f * (phi + om), &sap, &cap);
            float cbm, sbm; __sincosf(0.5f * (phi - om), &sbm, &cbm);
            float2 m00 = make_float2(cap * c, -sap * c);     // ep*c
            float2 m01 = make_float2(-cbm * s, -sbm * s);    // -em*s
            float2 m10 = make_float2(cbm * s, -sbm * s);     // conj(em)*s
            float2 m11 = make_float2(cap * c, sap * c);      // conj(ep)*c

            int p7 = 7 - w;
            int mask = 1 << p7;
            int bit = (d >> p7) & 1;
            __syncthreads();
            float2 me0 = a0[d], pa0 = a0[d ^ mask];
            float2 me1 = a1[d], pa1 = a1[d ^ mask];
            __syncthreads();
            float2 n0, n1;
            if (!bit) {
                n0 = cadd(cmul(m00, me0), cmul(m01, pa0));
                n1 = cadd(cmul(m00, me1), cmul(m01, pa1));
            } else {
                n0 = cadd(cmul(m10, pa0), cmul(m11, me0));
                n1 = cadd(cmul(m10, pa1), cmul(m11, me1));
            }
            a0[d] = n0; a1[d] = n1;
        }
        for (int w = 0; w < NQ - 1; w++) {
            int pc = 7 - w, pt = 6 - w;
            __syncthreads();
            int src = ((d >> pc) & 1) ? (d ^ (1 << pt)) : d;
            float2 v0 = a0[src], v1 = a1[src];
            __syncthreads();
            a0[d] = v0; a1[d] = v1;
        }
    }
    __syncthreads();

    float z = (d < QDIM / 2) ? 1.f : -1.f;
    float2 c0 = a0[d], c1 = a1[d];
    r0[d] = z * (c0.x * c0.x + c0.y * c0.y);
    r1[d] = z * (c1.x * c1.x + c1.y * c1.y);
    r2[d] = z * (c0.y * c1.x - c0.x * c1.y);
    __syncthreads();
    for (int off = QDIM / 2; off; off >>= 1) {
        if (d < off) { r0[d] += r0[d + off]; r1[d] += r1[d + off]; r2[d] += r2[d + off]; }
        __syncthreads();
    }
    float S00 = r0[0], S11 = r1[0], S01 = r2[0];
    __syncthreads();

    r0[d] = W[512 + d] + W[512 + QDIM + d];
    __syncthreads();
    for (int off = QDIM / 2; off; off >>= 1) {
        if (d < off) r0[d] += r0[d + off];
        __syncthreads();
    }
    if (d == 0) {
        float alpha = 0.5f * (S00 + S11);
        float beta  = 0.5f * (S00 - S11);
        float gamma = -S01;
        float R   = sqrtf(beta * beta + gamma * gamma);
        float phi = atan2f(gamma, beta);
        g_par[g][0] = r0[0];          // wsum
        g_par[g][1] = bv[0] - phi;    // theta offset (added in scan)
        g_par[g][2] = 0.5f * alpha;
        g_par[g][3] = 0.5f * R;
        g_par[g][4] = alpha;
        g_par[g][5] = R;
    }
}

// ---------------- Fused kernel: circuit (blocks 0-3) + xdot (blocks 4..4099) ----------------
// xdot no longer depends on circuit output (offsets are applied in the scan),
// so both live in one launch with no internal ordering requirement.
__global__ void prep_kernel(
    const float* __restrict__ X,
    const float* __restrict__ Wf, const float* __restrict__ Wi,
    const float* __restrict__ Wg, const float* __restrict__ Wo,
    const float* __restrict__ bfv, const float* __restrict__ biv,
    const float* __restrict__ bgv, const float* __restrict__ bov,
    const float* __restrict__ Pf, const float* __restrict__ Pi,
    const float* __restrict__ Pg, const float* __restrict__ Po)
{
    if (blockIdx.x < 4) {
        int g = blockIdx.x;
        const float* P  = (g == 0) ? Pf : (g == 1) ? Pi : (g == 2) ? Pg : Po;
        const float* W  = (g == 0) ? Wf : (g == 1) ? Wi : (g == 2) ? Wg : Wo;
        const float* bv = (g == 0) ? bfv : (g == 1) ? biv : (g == 2) ? bgv : bov;
        circuit_block(g, P, W, bv);
        return;
    }

    int warp = ((blockIdx.x - 4) * blockDim.x + threadIdx.x) >> 5;
    int lane = threadIdx.x & 31;
    if (warp >= T_STEPS * BATCH) return;

    const float4* xr = (const float4*)(X + (size_t)warp * DIM_IN);
    const float4* wf = (const float4*)Wf;
    const float4* wi = (const float4*)Wi;
    const float4* wg = (const float4*)Wg;
    const float4* wo = (const float4*)Wo;

    float sf = 0.f, si = 0.f, sg = 0.f, so = 0.f;
#pragma unroll
    for (int j = 0; j < 4; j++) {
        int k = lane + 32 * j;
        float4 xv = xr[k];
        float4 a = __ldg(wf + k); sf += xv.x * a.x + xv.y * a.y + xv.z * a.z + xv.w * a.w;
        float4 b = __ldg(wi + k); si += xv.x * b.x + xv.y * b.y + xv.z * b.z + xv.w * b.w;
        float4 c = __ldg(wg + k); sg += xv.x * c.x + xv.y * c.y + xv.z * c.z + xv.w * c.w;
        float4 e = __ldg(wo + k); so += xv.x * e.x + xv.y * e.y + xv.z * e.z + xv.w * e.w;
    }
#pragma unroll
    for (int o = 16; o; o >>= 1) {
        sf += __shfl_xor_sync(0xffffffffu, sf, o);
        si += __shfl_xor_sync(0xffffffffu, si, o);
        sg += __shfl_xor_sync(0xffffffffu, sg, o);
        so += __shfl_xor_sync(0xffffffffu, so, o);
    }
    if (lane == 0) g_xdot[warp] = make_float4(sf, si, sg, so);
}

// ---------------- Kernel C: scalar LSTM scan ----------------
// 128 independent scalar recurrences, 256 steps.
//   theta_g = (xd_g + off_g) + H*ws_g ; gate = act(alpha_g + R_g*cos(theta_g))
// sigmoid(u) = 0.5 + 0.5*tanh(u/2) via HW tanh; offsets applied at load time
// (off the H-dependence critical path). 8-deep register prefetch ring.
__global__ void scan_kernel()
{
    int b = threadIdx.x;

    float ws_f = g_par[0][0], A2_f = g_par[0][2], R2_f = g_par[0][3];
    float ws_i = g_par[1][0], A2_i = g_par[1][2], R2_i = g_par[1][3];
    float ws_g = g_par[2][0], A_g  = g_par[2][4], R_g  = g_par[2][5];
    float ws_o = g_par[3][0], A2_o = g_par[3][2], R2_o = g_par[3][3];
    float off_f = g_par[0][1], off_i = g_par[1][1], off_g = g_par[2][1], off_o = g_par[3][1];

    float H = 0.f, C = 0.f;

    const float4* X = g_xdot;
#define LOADADJ(t) \
    ({ float4 v_ = X[(t) * BATCH + b]; \
       v_.x += off_f; v_.y += off_i; v_.z += off_g; v_.w += off_o; v_; })

    float4 q[8];
#pragma unroll
    for (int j = 0; j < 8; j++) q[j] = LOADADJ(j);

#define STEP(xd, t)                                                   \
    {                                                                 \
        float cf = __cosf(fmaf(H, ws_f, (xd).x));                     \
        float ci = __cosf(fmaf(H, ws_i, (xd).y));                     \
        float cg = __cosf(fmaf(H, ws_g, (xd).z));                     \
        float co = __cosf(fmaf(H, ws_o, (xd).w));                     \
        float fv = fmaf(htanh(fmaf(R2_f, cf, A2_f)), 0.5f, 0.5f);     \
        float iv = fmaf(htanh(fmaf(R2_i, ci, A2_i)), 0.5f, 0.5f);     \
        float gv = htanh(fmaf(R_g, cg, A_g));                         \
        float ov = fmaf(htanh(fmaf(R2_o, co, A2_o)), 0.5f, 0.5f);     \
        C = fmaf(fv, C, iv * gv);                                     \
        H = ov * htanh(C);                                            \
        g_H[(t) * BATCH + b] = H;                                     \
    }

#pragma unroll 1
    for (int t = 0; t < T_STEPS; t += 8) {
#pragma unroll
        for (int j = 0; j < 8; j++) {
            float4 cur = q[j];
            if (t + 8 + j < T_STEPS) q[j] = LOADADJ(t + 8 + j);
            STEP(cur, t + j);
        }
    }
#undef STEP
#undef LOADADJ
    g_Cfin[b] = C;
}

// ---------------- Kernel D: broadcast scalars into the full output ----------------
// 1 float4 per thread, perfectly coalesced; streaming stores (write-once data).
// d_out layout: outputs (T,B,512) ++ hx (B,512) ++ cx (B,512).
__global__ void bcast_kernel(float4* __restrict__ out)
{
    const unsigned OUT4 = (unsigned)T_STEPS * BATCH * (HID / 4); // 4,194,304
    const unsigned HB4  = (unsigned)BATCH * (HID / 4);           // 16,384
    unsigned i = blockIdx.x * blockDim.x + threadIdx.x;          // float4 index
    float v;
    if (i < OUT4) {
        v = g_H[i >> 7];                                         // (t*B+b) = i/128
    } else if (i < OUT4 + HB4) {
        v = g_H[(T_STEPS - 1) * BATCH + ((i - OUT4) >> 7)];      // hx
    } else if (i < OUT4 + 2 * HB4) {
        v = g_Cfin[(i - OUT4 - HB4) >> 7];                       // cx
    } else {
        return;
    }
    __stcs(out + i, make_float4(v, v, v, v));
}

// ---------------- launch ----------------
extern "C" void kernel_launch(void* const* d_in, const int* in_sizes, int n_in,
                              void* d_out, int out_size)
{
    const float* X  = (const float*)d_in[0];
    const float* Wf = (const float*)d_in[1];
    const float* bf = (const float*)d_in[2];
    const float* Pf = (const float*)d_in[3];
    const float* Wi = (const float*)d_in[4];
    const float* bi = (const float*)d_in[5];
    const float* Pi = (const float*)d_in[6];
    const float* Wg = (const float*)d_in[7];
    const float* bg = (const float*)d_in[8];
    const float* Pg = (const float*)d_in[9];
    const float* Wo = (const float*)d_in[10];
    const float* bo = (const float*)d_in[11];
    const float* Po = (const float*)d_in[12];

    // blocks 0-3: circuits; blocks 4..4099: xdot (32768 warp-rows / 8 warps per block)
    prep_kernel<<<4 + (T_STEPS * BATCH) / 8, 256>>>(
        X, Wf, Wi, Wg, Wo, bf, bi, bg, bo, Pf, Pi, Pg, Po);

    scan_kernel<<<1, BATCH>>>();

    // 4,194,304 + 32,768 float4 = 4,227,072 = 16512 * 256
    bcast_kernel<<<16512, 256>>>((float4*)d_out);
}